// round 14
// baseline (speedup 1.0000x reference)
#include <cuda_runtime.h>
#include <math.h>

#define Dd 2048
#define Hh 1152
#define Kk 64
#define NAa 18
#define Rr 10

// ---------------- scratch (device globals) ----------------------------------
__device__ __align__(16) float d_s[Dd];
__device__ __align__(16) float d_u[Hh];
__device__ __align__(16) float d_gpart[4 * Dd];   // Whh_m@h_t + biases
__device__ __align__(16) float d_gact[4 * Dd];    // full manager gate preact
__device__ __align__(16) float d_hsum[Dd];        // sum_r hn_m[r]
__device__ __align__(16) float d_hnew[Dd];        // new manager hidden
__device__ float d_wA[Kk];                        // Wphi @ goalsum
__device__ float d_wB[Kk];                        // Wphi @ (hsum - hn_m[tick])
__device__ float d_w[Kk];
__device__ float d_scal[2];                       // inv_norm, mv_sum
__device__ float d_cosv[Rr];                      // r=0..8 by blk 512, r=9 by 514
__device__ float d_wval;
__device__ int d_mdone, d_aux, d_f1, d_wcnt, d_p2;  // reset ONLY by final block

__device__ __forceinline__ float sigm(float x) { return 1.f / (1.f + expf(-x)); }

// warp dot over NIT*32 float4s (lane-strided), result on all lanes
template <int NIT>
__device__ __forceinline__ float wdot(const float4* __restrict__ a,
                                      const float4* __restrict__ b, int lane) {
    float acc = 0.f;
#pragma unroll
    for (int i = 0; i < NIT; i++) {
        float4 x = a[lane + i * 32];
        float4 y = b[lane + i * 32];
        acc = fmaf(x.x, y.x, acc);
        acc = fmaf(x.y, y.y, acc);
        acc = fmaf(x.z, y.z, acc);
        acc = fmaf(x.w, y.w, acc);
    }
#pragma unroll
    for (int o = 16; o; o >>= 1) acc += __shfl_xor_sync(0xffffffffu, acc, o);
    return acc;
}

__device__ __forceinline__ void wait_ctr(int* ctr, int tgt) {
    if (threadIdx.x == 0) {
        volatile int* c = ctr;
        while (*c < tgt) __nanosleep(64);
        __threadfence();
    }
    __syncthreads();
}

// ---------------- k1: wave 1 (8 KB smem) ---------------------------------------
// blocks [0,256):      s rows, 1 row/warp (z recomputed in smem)
// blocks [256,832):    worker gate rows, 1 row/warp, 2 units/block
// blocks [832,1856):   Whh_m rows -> d_gpart, 1 row/warp
// blocks [1856,1864):  hsum
// blocks [1864,1872):  wA/wB rows (two-pass staging in the same smem buffer)
__global__ void __launch_bounds__(256)
k1(const float* __restrict__ x, const float* __restrict__ Wp,
   const float* __restrict__ bp, const float* __restrict__ Wms,
   const float* __restrict__ bms, const float* __restrict__ Wih_w,
   const float* __restrict__ Whh_w, const float* __restrict__ bih_w,
   const float* __restrict__ bhh_w, const float* __restrict__ hn_w,
   const float* __restrict__ cn_w, const float* __restrict__ Whh_m,
   const float* __restrict__ bih_m, const float* __restrict__ bhh_m,
   const float* __restrict__ hn_m, const float* __restrict__ goals,
   const float* __restrict__ Wphi, const int* __restrict__ tickp) {
    const int warp = threadIdx.x >> 5, lane = threadIdx.x & 31;
    const int b = blockIdx.x;
    __shared__ __align__(16) float zs[Dd];
    __shared__ float gsh[8];

    if (b < 832) {
        float x0 = x[0], x1 = x[1];
        for (int i = threadIdx.x; i < Dd; i += 256) {
            float v = fmaf(Wp[2 * i], x0, fmaf(Wp[2 * i + 1], x1, bp[i]));
            zs[i] = fmaxf(v, 0.f);
        }
        __syncthreads();
        if (b < 256) {
            int row = b * 8 + warp;
            float v = wdot<16>((const float4*)(Wms + (size_t)row * Dd),
                               (const float4*)zs, lane);
            if (!lane) d_s[row] = fmaxf(v + bms[row], 0.f);
        } else {
            const int wb = b - 256;
            const int unit = wb * 2 + (warp >> 2);
            const int q = warp & 3;
            const int row = unit + q * Hh;
            float a = wdot<16>((const float4*)(Wih_w + (size_t)row * Dd),
                               (const float4*)zs, lane);
            float c = wdot<9>((const float4*)(Whh_w + (size_t)row * Hh),
                              (const float4*)hn_w, lane);
            if (!lane) gsh[warp] = a + c + bih_w[row] + bhh_w[row];
            __syncthreads();
            if ((threadIdx.x & 127) == 0) {
                const int half = threadIdx.x >> 7;
                const int j = wb * 2 + half;
                const float* g = gsh + half * 4;
                float ig = sigm(g[0]), fg = sigm(g[1]);
                float g2 = tanhf(g[2]), og = sigm(g[3]);
                float c2 = fmaf(fg, cn_w[j], ig * g2);
                d_u[j] = og * tanhf(c2);
            }
        }
    } else if (b < 1856) {
        const int tick = *tickp;
        const int row = (b - 832) * 8 + warp;
        float v = wdot<16>((const float4*)(Whh_m + (size_t)row * Dd),
                           (const float4*)(hn_m + (size_t)tick * Dd), lane);
        if (!lane) d_gpart[row] = v + bih_m[row] + bhh_m[row];
    } else if (b < 1864) {
        const int i = (b - 1856) * 256 + threadIdx.x;
        float a = 0.f;
#pragma unroll
        for (int r = 0; r < Rr; r++) a += hn_m[(size_t)r * Dd + i];
        d_hsum[i] = a;
    } else {
        // wA/wB: two passes over the SAME 8KB smem buffer
        const int tick = *tickp;
        const int row = (b - 1864) * 8 + warp;
        const float4* wrow = (const float4*)(Wphi + (size_t)row * Dd);

        for (int i = threadIdx.x; i < Dd; i += 256) {
            float ga = 0.f;
#pragma unroll
            for (int r = 1; r < Rr; r++) ga += goals[(size_t)r * Dd + i];
            zs[i] = ga;
        }
        __syncthreads();
        float va = wdot<16>(wrow, (const float4*)zs, lane);
        __syncthreads();
        for (int i = threadIdx.x; i < Dd; i += 256) {
            float ha = 0.f;
#pragma unroll
            for (int r = 0; r < Rr; r++)
                if (r != tick) ha += hn_m[(size_t)r * Dd + i];
            zs[i] = ha;
        }
        __syncthreads();
        float vb = wdot<16>(wrow, (const float4*)zs, lane);
        if (!lane) { d_wA[row] = va; d_wB[row] = vb; }
    }
}

// ---------------- k2: wave 2 + in-kernel tail, grid 580 <= residency 888 -------
// blocks [0,512): Wih_m rows (2/warp) + gpart -> gact    [count mdone]
// block  512:     cosines r=0..8                         [count aux]
// block  513:     w_value                                [count aux]
// block  514:     pointwise LSTM (spin mdone) -> f1; cosv[9]; out[20]; [set p2]
// blocks 515..578: w rows (spin f1)                      [count wcnt]
// block  579:     FINAL: spin wcnt+aux+p2; logits; out[18],out[19]; reset flags
__global__ void __launch_bounds__(256, 6)
k2(const float* __restrict__ Wih_m, const float* __restrict__ goals,
   const float* __restrict__ states, const float* __restrict__ Wc,
   const float* __restrict__ bc, const float* __restrict__ hn_m,
   const float* __restrict__ cn_m, const float* __restrict__ Wmv,
   const float* __restrict__ Wphi, const float* __restrict__ bmv,
   const int* __restrict__ tickp, float* __restrict__ out) {
    const int tid = threadIdx.x;
    const int warp = tid >> 5, lane = tid & 31;
    const int b = blockIdx.x;
    __shared__ float red[24];

    if (b < 512) {
        const int r0 = b * 16 + warp;
        float v0 = wdot<16>((const float4*)(Wih_m + (size_t)r0 * Dd),
                            (const float4*)d_s, lane);
        const int r1 = r0 + 8;
        float v1 = wdot<16>((const float4*)(Wih_m + (size_t)r1 * Dd),
                            (const float4*)d_s, lane);
        if (!lane) {
            d_gact[r0] = v0 + d_gpart[r0];
            d_gact[r1] = v1 + d_gpart[r1];
        }
        __syncthreads();
        if (tid == 0) { __threadfence(); atomicAdd(&d_mdone, 1); }
    } else if (b == 512) {
        for (int r = warp; r < Rr - 1; r += 8) {
            const float* st = states + (size_t)(r + 1) * Dd;
            const float* gl = goals + (size_t)(r + 1) * Dd;
            float num = 0.f, dd = 0.f, gg = 0.f;
            for (int d = lane; d < Dd; d += 32) {
                float diff = d_s[d] - st[d];
                float go = gl[d];
                num = fmaf(diff, go, num);
                dd = fmaf(diff, diff, dd);
                gg = fmaf(go, go, gg);
            }
#pragma unroll
            for (int o = 16; o; o >>= 1) {
                num += __shfl_xor_sync(0xffffffffu, num, o);
                dd += __shfl_xor_sync(0xffffffffu, dd, o);
                gg += __shfl_xor_sync(0xffffffffu, gg, o);
            }
            if (!lane)
                d_cosv[r] = num / (fmaxf(sqrtf(dd), 1e-8f) *
                                   fmaxf(sqrtf(gg), 1e-8f));
        }
        __syncthreads();
        if (tid == 0) { __threadfence(); atomicAdd(&d_aux, 1); }
    } else if (b == 513) {
        __shared__ float r2[256];
        float wv = 0.f;
        for (int j = tid; j < Hh; j += 256) wv = fmaf(d_u[j], Wc[j], wv);
        r2[tid] = wv;
        __syncthreads();
        for (int s = 128; s; s >>= 1) {
            if (tid < s) r2[tid] += r2[tid + s];
            __syncthreads();
        }
        if (tid == 0) {
            d_wval = r2[0] + bc[0];
            __threadfence();
            atomicAdd(&d_aux, 1);
        }
    } else if (b == 514) {
        // ---- pointwise manager cell (spins only on gact) ----
        __shared__ __align__(16) float ghat[Dd];
        __shared__ float sc[2];
        wait_ctr(&d_mdone, 512);
        const int tick = *tickp;
        float acc_sq = 0.f, acc_mv = 0.f;
#pragma unroll 2
        for (int rep = 0; rep < 8; rep++) {
            const int i = tid + rep * 256;
            float g0 = d_gact[i];
            float g1 = d_gact[i + Dd];
            float g2 = d_gact[i + 2 * Dd];
            float g3 = d_gact[i + 3 * Dd];
            float ig = sigm(g0), fg = sigm(g1);
            float gt = tanhf(g2), og = sigm(g3);
            float c2 = fmaf(fg, cn_m[(size_t)tick * Dd + i], ig * gt);
            float hnew = og * tanhf(c2);
            d_hnew[i] = hnew;
            float gh = (d_hsum[i] - hn_m[(size_t)tick * Dd + i] + hnew) * 0.1f;
            ghat[i] = gh;
            acc_sq = fmaf(gh, gh, acc_sq);
            acc_mv = fmaf(gh, Wmv[i], acc_mv);
        }
#pragma unroll
        for (int o = 16; o; o >>= 1) {
            acc_sq += __shfl_xor_sync(0xffffffffu, acc_sq, o);
            acc_mv += __shfl_xor_sync(0xffffffffu, acc_mv, o);
        }
        if (!lane) { red[warp] = acc_sq; red[warp + 8] = acc_mv; }
        __syncthreads();
        if (tid == 0) {
            float sa = 0.f, sb = 0.f;
#pragma unroll
            for (int q = 0; q < 8; q++) { sa += red[q]; sb += red[q + 8]; }
            float inv = 1.f / fmaxf(sqrtf(sa), 1e-12f);
            sc[0] = inv;
            d_scal[0] = inv;
            out[20] = sb + bmv[0];
            __threadfence();
            atomicExch(&d_f1, 1);       // release hnew + inv_norm to w blocks
        }
        __syncthreads();

        // last cosine (r=9, goal = ghat*inv), block-wide, into d_cosv[9]
        const float inv_norm = sc[0];
        const float* st = states + (size_t)Rr * Dd;
        float num = 0.f, dd = 0.f, gg = 0.f;
        for (int d = tid; d < Dd; d += 256) {
            float diff = d_s[d] - st[d];
            float go = ghat[d] * inv_norm;
            num = fmaf(diff, go, num);
            dd = fmaf(diff, diff, dd);
            gg = fmaf(go, go, gg);
        }
#pragma unroll
        for (int o = 16; o; o >>= 1) {
            num += __shfl_xor_sync(0xffffffffu, num, o);
            dd += __shfl_xor_sync(0xffffffffu, dd, o);
            gg += __shfl_xor_sync(0xffffffffu, gg, o);
        }
        if (!lane) { red[warp] = num; red[warp + 8] = dd; red[warp + 16] = gg; }
        __syncthreads();
        if (tid == 0) {
            float n = 0.f, a = 0.f, g = 0.f;
#pragma unroll
            for (int q = 0; q < 8; q++) {
                n += red[q]; a += red[q + 8]; g += red[q + 16];
            }
            d_cosv[Rr - 1] =
                n / (fmaxf(sqrtf(a), 1e-8f) * fmaxf(sqrtf(g), 1e-8f));
            __threadfence();
            atomicExch(&d_p2, 1);
        }
    } else if (b < 579) {
        // ---- w[k] = wA[k] + 0.1*inv*(wB[k] + Wphi[k]@hnew) ----
        wait_ctr(&d_f1, 1);
        const int k = b - 515;
        const float4* wp = (const float4*)(Wphi + (size_t)k * Dd);
        const float4* hp = (const float4*)d_hnew;
        float acc = 0.f;
#pragma unroll
        for (int rep = 0; rep < 2; rep++) {
            float4 a = wp[tid + rep * 256];
            float4 h = hp[tid + rep * 256];
            acc = fmaf(a.x, h.x, acc);
            acc = fmaf(a.y, h.y, acc);
            acc = fmaf(a.z, h.z, acc);
            acc = fmaf(a.w, h.w, acc);
        }
#pragma unroll
        for (int o = 16; o; o >>= 1) acc += __shfl_xor_sync(0xffffffffu, acc, o);
        if (!lane) red[warp] = acc;
        __syncthreads();
        if (tid == 0) {
            float s = 0.f;
#pragma unroll
            for (int q = 0; q < 8; q++) s += red[q];
            d_w[k] = fmaf(0.1f * d_scal[0], d_wB[k] + s, d_wA[k]);
            __threadfence();
            atomicAdd(&d_wcnt, 1);
        }
    } else {
        // ---- FINAL block: waits on EVERYTHING, then outputs + reset ----
        wait_ctr(&d_wcnt, Kk);
        wait_ctr(&d_aux, 2);
        wait_ctr(&d_p2, 1);
        __shared__ float wvec[Kk];
        if (tid < Kk) wvec[tid] = d_w[tid];
        __syncthreads();
        for (int a = warp; a < NAa; a += 8) {
            float v = fmaf(d_u[a * Kk + lane], wvec[lane],
                           d_u[a * Kk + 32 + lane] * wvec[32 + lane]);
#pragma unroll
            for (int o = 16; o; o >>= 1)
                v += __shfl_xor_sync(0xffffffffu, v, o);
            if (!lane) out[a] = v;
        }
        __syncthreads();
        if (tid == 0) {
            float cs = 0.f;
#pragma unroll
            for (int r = 0; r < Rr; r++) cs += d_cosv[r];
            out[18] = 2048.f * cs * 0.1f;
            out[19] = d_wval;
            // safe reset: all waits above are globally satisfied by now
            d_mdone = 0; d_aux = 0; d_f1 = 0; d_wcnt = 0; d_p2 = 0;
        }
    }
}

// ---------------- launch ------------------------------------------------------
extern "C" void kernel_launch(void* const* d_in, const int* in_sizes, int n_in,
                              void* d_out, int out_size) {
    const float* x      = (const float*)d_in[0];
    const float* Wp     = (const float*)d_in[1];
    const float* bp     = (const float*)d_in[2];
    const float* Wms    = (const float*)d_in[3];
    const float* bms    = (const float*)d_in[4];
    const float* Wih_m  = (const float*)d_in[5];
    const float* Whh_m  = (const float*)d_in[6];
    const float* bih_m  = (const float*)d_in[7];
    const float* bhh_m  = (const float*)d_in[8];
    const float* hn_m   = (const float*)d_in[9];
    const float* cn_m   = (const float*)d_in[10];
    const float* Wmv    = (const float*)d_in[11];
    const float* bmv    = (const float*)d_in[12];
    const float* Wih_w  = (const float*)d_in[13];
    const float* Whh_w  = (const float*)d_in[14];
    const float* bih_w  = (const float*)d_in[15];
    const float* bhh_w  = (const float*)d_in[16];
    const float* hn_w   = (const float*)d_in[17];
    const float* cn_w   = (const float*)d_in[18];
    const float* Wphi   = (const float*)d_in[19];
    const float* Wc     = (const float*)d_in[20];
    const float* bc     = (const float*)d_in[21];
    const float* states = (const float*)d_in[22];
    const float* goals  = (const float*)d_in[23];
    const int*   tick   = (const int*)d_in[24];
    float* out = (float*)d_out;

    k1<<<1872, 256>>>(x, Wp, bp, Wms, bms, Wih_w, Whh_w, bih_w, bhh_w,
                      hn_w, cn_w, Whh_m, bih_m, bhh_m, hn_m, goals, Wphi,
                      tick);
    k2<<<580, 256>>>(Wih_m, goals, states, Wc, bc, hn_m, cn_m, Wmv, Wphi,
                     bmv, tick, out);
}

// round 15
// speedup vs baseline: 1.2983x; 1.2983x over previous
#include <cuda_runtime.h>
#include <math.h>

#define Dd 2048
#define Hh 1152
#define Kk 64
#define NAa 18
#define Rr 10

// ---------------- scratch (device globals) ----------------------------------
__device__ __align__(16) float d_s[Dd];
__device__ __align__(16) float d_u[Hh];
__device__ __align__(16) float d_gact[4 * Dd];    // full manager gate preact
__device__ __align__(16) float d_hsum[Dd];        // sum_r hn_m[r]
__device__ __align__(16) float d_goalsum[Dd];     // sum_{r=1..9} goals[r]
__device__ float d_cosv[Rr];                      // r=0..8 (k1); r=9 in k2
__device__ float d_wval;
__device__ int d_sdone, d_udone;                  // zero-init; reset in k2

__device__ __forceinline__ float sigm(float x) { return 1.f / (1.f + expf(-x)); }

// warp dot over NIT*32 float4s (lane-strided), result on all lanes
template <int NIT>
__device__ __forceinline__ float wdot(const float4* __restrict__ a,
                                      const float4* __restrict__ b, int lane) {
    float acc = 0.f;
#pragma unroll
    for (int i = 0; i < NIT; i++) {
        float4 x = a[lane + i * 32];
        float4 y = b[lane + i * 32];
        acc = fmaf(x.x, y.x, acc);
        acc = fmaf(x.y, y.y, acc);
        acc = fmaf(x.z, y.z, acc);
        acc = fmaf(x.w, y.w, acc);
    }
#pragma unroll
    for (int o = 16; o; o >>= 1) acc += __shfl_xor_sync(0xffffffffu, acc, o);
    return acc;
}

__device__ __forceinline__ void wait_ctr(int* ctr, int tgt) {
    if (threadIdx.x == 0) {
        volatile int* c = ctr;
        while (*c < tgt) __nanosleep(64);
        __threadfence();
    }
    __syncthreads();
}

// ---------------- k1_mega: single 209 MB wave (grid 1874) ----------------------
// blocks [0,256):     s rows, 1 row/warp (z recomputed in smem)   [count sdone]
// blocks [256,832):   worker gate rows, 2 units/block             [count udone]
// blocks [832,840):   hsum
// blocks [840,848):   goalsum
// block  848:         cosines r=0..8                              [spin sdone]
// block  849:         w_value                                     [spin udone]
// blocks [850,1874):  manager: FULL gate = Wih_m@s + Whh_m@h      [spin sdone]
__global__ void __launch_bounds__(256)
k1_mega(const float* __restrict__ x, const float* __restrict__ Wp,
        const float* __restrict__ bp, const float* __restrict__ Wms,
        const float* __restrict__ bms, const float* __restrict__ Wih_w,
        const float* __restrict__ Whh_w, const float* __restrict__ bih_w,
        const float* __restrict__ bhh_w, const float* __restrict__ hn_w,
        const float* __restrict__ cn_w, const float* __restrict__ Wih_m,
        const float* __restrict__ Whh_m, const float* __restrict__ bih_m,
        const float* __restrict__ bhh_m, const float* __restrict__ hn_m,
        const float* __restrict__ goals, const float* __restrict__ states,
        const float* __restrict__ Wc, const float* __restrict__ bc,
        const int* __restrict__ tickp) {
    const int tid = threadIdx.x;
    const int warp = tid >> 5, lane = tid & 31;
    const int b = blockIdx.x;
    __shared__ __align__(16) float vs[Dd];     // z / staged d_s
    __shared__ float gsh[8];

    if (b < 832) {
        // z = relu(Wp@x + bp) recomputed into smem
        float x0 = x[0], x1 = x[1];
        for (int i = tid; i < Dd; i += 256) {
            float v = fmaf(Wp[2 * i], x0, fmaf(Wp[2 * i + 1], x1, bp[i]));
            vs[i] = fmaxf(v, 0.f);
        }
        __syncthreads();
        if (b < 256) {
            int row = b * 8 + warp;
            float v = wdot<16>((const float4*)(Wms + (size_t)row * Dd),
                               (const float4*)vs, lane);
            if (!lane) d_s[row] = fmaxf(v + bms[row], 0.f);
            __syncthreads();
            if (tid == 0) { __threadfence(); atomicAdd(&d_sdone, 1); }
        } else {
            const int wb = b - 256;
            const int unit = wb * 2 + (warp >> 2);
            const int q = warp & 3;
            const int row = unit + q * Hh;
            float a = wdot<16>((const float4*)(Wih_w + (size_t)row * Dd),
                               (const float4*)vs, lane);
            float c = wdot<9>((const float4*)(Whh_w + (size_t)row * Hh),
                              (const float4*)hn_w, lane);
            if (!lane) gsh[warp] = a + c + bih_w[row] + bhh_w[row];
            __syncthreads();
            if ((tid & 127) == 0) {
                const int half = tid >> 7;
                const int j = wb * 2 + half;
                const float* g = gsh + half * 4;
                float ig = sigm(g[0]), fg = sigm(g[1]);
                float g2 = tanhf(g[2]), og = sigm(g[3]);
                float c2 = fmaf(fg, cn_w[j], ig * g2);
                d_u[j] = og * tanhf(c2);
            }
            __syncthreads();
            if (tid == 0) { __threadfence(); atomicAdd(&d_udone, 1); }
        }
    } else if (b < 840) {
        const int i = (b - 832) * 256 + tid;
        float a = 0.f;
#pragma unroll
        for (int r = 0; r < Rr; r++) a += hn_m[(size_t)r * Dd + i];
        d_hsum[i] = a;
    } else if (b < 848) {
        const int d = (b - 840) * 256 + tid;
        float a = 0.f;
#pragma unroll
        for (int r = 1; r < Rr; r++) a += goals[(size_t)r * Dd + d];
        d_goalsum[d] = a;
    } else if (b == 848) {
        // cosines r=0..8 (needs s)
        wait_ctr(&d_sdone, 256);
        for (int r = warp; r < Rr - 1; r += 8) {
            const float* st = states + (size_t)(r + 1) * Dd;
            const float* gl = goals + (size_t)(r + 1) * Dd;
            float num = 0.f, dd = 0.f, gg = 0.f;
            for (int d = lane; d < Dd; d += 32) {
                float diff = d_s[d] - st[d];
                float go = gl[d];
                num = fmaf(diff, go, num);
                dd = fmaf(diff, diff, dd);
                gg = fmaf(go, go, gg);
            }
#pragma unroll
            for (int o = 16; o; o >>= 1) {
                num += __shfl_xor_sync(0xffffffffu, num, o);
                dd += __shfl_xor_sync(0xffffffffu, dd, o);
                gg += __shfl_xor_sync(0xffffffffu, gg, o);
            }
            if (!lane)
                d_cosv[r] = num / (fmaxf(sqrtf(dd), 1e-8f) *
                                   fmaxf(sqrtf(gg), 1e-8f));
        }
    } else if (b == 849) {
        // w_value (needs u)
        wait_ctr(&d_udone, 576);
        __shared__ float red[256];
        float wv = 0.f;
        for (int j = tid; j < Hh; j += 256) wv = fmaf(d_u[j], Wc[j], wv);
        red[tid] = wv;
        __syncthreads();
        for (int s = 128; s; s >>= 1) {
            if (tid < s) red[tid] += red[tid + s];
            __syncthreads();
        }
        if (tid == 0) d_wval = red[0] + bc[0];
    } else {
        // manager: full gate preact (needs s)
        wait_ctr(&d_sdone, 256);
        // stage d_s into smem (proven s/worker-branch geometry)
        {
            const float4* sp = (const float4*)d_s;
            float4* dp = (float4*)vs;
            for (int i = tid; i < Dd / 4; i += 256) dp[i] = sp[i];
        }
        __syncthreads();
        const int tick = *tickp;
        const int row = (b - 850) * 8 + warp;
        float a = wdot<16>((const float4*)(Wih_m + (size_t)row * Dd),
                           (const float4*)vs, lane);
        float c = wdot<16>((const float4*)(Whh_m + (size_t)row * Dd),
                           (const float4*)(hn_m + (size_t)tick * Dd), lane);
        if (!lane) d_gact[row] = a + c + bih_m[row] + bhh_m[row];
    }
}

// ---------------- k2_final: 1 block, 1024 threads ------------------------------
// pointwise -> ghat/gsum (smem) -> w = Wphi@gsum -> logits, cos9, outputs
// out: [0:18] logits, [18] intrinsic, [19] w_value, [20] m_value
__global__ void __launch_bounds__(1024)
k2_final(const float* __restrict__ hn_m, const float* __restrict__ cn_m,
         const float* __restrict__ Wmv, const float* __restrict__ Wphi,
         const float* __restrict__ states, const float* __restrict__ bmv,
         const int* __restrict__ tickp, float* __restrict__ out) {
    const int tid = threadIdx.x;
    const int warp = tid >> 5, lane = tid & 31;
    __shared__ float red[64];
    __shared__ float sc[4];
    __shared__ float wvec[Kk];
    __shared__ __align__(16) float ghat_s[Dd];
    __shared__ __align__(16) float gsum[Dd];

    const int tick = *tickp;
    float acc_sq = 0.f, acc_mv = 0.f;
#pragma unroll
    for (int rep = 0; rep < 2; rep++) {
        const int i = tid + rep * 1024;
        float g0 = d_gact[i];
        float g1 = d_gact[i + Dd];
        float g2 = d_gact[i + 2 * Dd];
        float g3 = d_gact[i + 3 * Dd];
        float ig = sigm(g0), fg = sigm(g1);
        float gt = tanhf(g2), og = sigm(g3);
        float c2 = fmaf(fg, cn_m[(size_t)tick * Dd + i], ig * gt);
        float hnew = og * tanhf(c2);
        float hs = d_hsum[i] - hn_m[(size_t)tick * Dd + i] + hnew;
        float gh = hs * 0.1f;
        ghat_s[i] = gh;
        acc_sq = fmaf(gh, gh, acc_sq);
        acc_mv = fmaf(gh, Wmv[i], acc_mv);
    }
#pragma unroll
    for (int o = 16; o; o >>= 1) {
        acc_sq += __shfl_xor_sync(0xffffffffu, acc_sq, o);
        acc_mv += __shfl_xor_sync(0xffffffffu, acc_mv, o);
    }
    if (!lane) { red[warp] = acc_sq; red[warp + 32] = acc_mv; }
    __syncthreads();
    if (tid == 0) {
        float sa = 0.f, sb = 0.f;
#pragma unroll
        for (int q = 0; q < 32; q++) { sa += red[q]; sb += red[q + 32]; }
        sc[0] = 1.f / fmaxf(sqrtf(sa), 1e-12f);
        sc[1] = sb;
    }
    __syncthreads();

    const float inv_norm = sc[0];
    for (int d = tid; d < Dd; d += 1024)
        gsum[d] = fmaf(ghat_s[d], inv_norm, d_goalsum[d]);
    __syncthreads();

    // w = Wphi @ gsum : 64 rows, 2 per warp (32 warps, high MLP)
#pragma unroll
    for (int rep = 0; rep < 2; rep++) {
        const int k = warp + rep * 32;
        float v = wdot<16>((const float4*)(Wphi + (size_t)k * Dd),
                           (const float4*)gsum, lane);
        if (!lane) wvec[k] = v;
    }
    __syncthreads();

    if (warp < NAa) {
        // logits[a] = u[a*64 .. a*64+63] . wvec
        float v = fmaf(d_u[warp * Kk + lane], wvec[lane],
                       d_u[warp * Kk + 32 + lane] * wvec[32 + lane]);
#pragma unroll
        for (int o = 16; o; o >>= 1) v += __shfl_xor_sync(0xffffffffu, v, o);
        if (!lane) out[warp] = v;
    } else if (warp == NAa) {
        // last cosine (r = 9, goal = g)
        const float* st = states + (size_t)Rr * Dd;
        float num = 0.f, dd = 0.f, gg = 0.f;
        for (int d = lane; d < Dd; d += 32) {
            float diff = d_s[d] - st[d];
            float go = ghat_s[d] * inv_norm;
            num = fmaf(diff, go, num);
            dd = fmaf(diff, diff, dd);
            gg = fmaf(go, go, gg);
        }
#pragma unroll
        for (int o = 16; o; o >>= 1) {
            num += __shfl_xor_sync(0xffffffffu, num, o);
            dd += __shfl_xor_sync(0xffffffffu, dd, o);
            gg += __shfl_xor_sync(0xffffffffu, gg, o);
        }
        if (!lane)
            sc[2] = num / (fmaxf(sqrtf(dd), 1e-8f) * fmaxf(sqrtf(gg), 1e-8f));
    }
    __syncthreads();
    if (tid == 0) {
        float cs = sc[2];
#pragma unroll
        for (int r = 0; r < Rr - 1; r++) cs += d_cosv[r];
        out[18] = 2048.f * cs * 0.1f;
        out[19] = d_wval;
        out[20] = sc[1] + bmv[0];
        d_sdone = 0;                    // safe reset: k1 fully retired
        d_udone = 0;
    }
}

// ---------------- launch ------------------------------------------------------
extern "C" void kernel_launch(void* const* d_in, const int* in_sizes, int n_in,
                              void* d_out, int out_size) {
    const float* x      = (const float*)d_in[0];
    const float* Wp     = (const float*)d_in[1];
    const float* bp     = (const float*)d_in[2];
    const float* Wms    = (const float*)d_in[3];
    const float* bms    = (const float*)d_in[4];
    const float* Wih_m  = (const float*)d_in[5];
    const float* Whh_m  = (const float*)d_in[6];
    const float* bih_m  = (const float*)d_in[7];
    const float* bhh_m  = (const float*)d_in[8];
    const float* hn_m   = (const float*)d_in[9];
    const float* cn_m   = (const float*)d_in[10];
    const float* Wmv    = (const float*)d_in[11];
    const float* bmv    = (const float*)d_in[12];
    const float* Wih_w  = (const float*)d_in[13];
    const float* Whh_w  = (const float*)d_in[14];
    const float* bih_w  = (const float*)d_in[15];
    const float* bhh_w  = (const float*)d_in[16];
    const float* hn_w   = (const float*)d_in[17];
    const float* cn_w   = (const float*)d_in[18];
    const float* Wphi   = (const float*)d_in[19];
    const float* Wc     = (const float*)d_in[20];
    const float* bc     = (const float*)d_in[21];
    const float* states = (const float*)d_in[22];
    const float* goals  = (const float*)d_in[23];
    const int*   tick   = (const int*)d_in[24];
    float* out = (float*)d_out;

    k1_mega<<<1874, 256>>>(x, Wp, bp, Wms, bms, Wih_w, Whh_w, bih_w, bhh_w,
                           hn_w, cn_w, Wih_m, Whh_m, bih_m, bhh_m, hn_m,
                           goals, states, Wc, bc, tick);
    k2_final<<<1, 1024>>>(hn_m, cn_m, Wmv, Wphi, states, bmv, tick, out);
}